// round 1
// baseline (speedup 1.0000x reference)
#include <cuda_runtime.h>

// Nested-square smoothing-kernel weight, computed exactly as the Python
// gen_kernel does (double math, then f32 store): ring index m = distance to
// the nearest kernel edge; value = (1/(center+1)) * (m+1).
__device__ __forceinline__ float kernel_val(int i, int j, int lw, int center) {
    int m = min(min(i, j), min(lw - 1 - i, lw - 1 - j));
    return (float)((1.0 / (double)(center + 1)) * (double)(m + 1));
}

// Stamp the two 7x7 (general lw x lw) blobs into the zeroed output.
// blockIdx.x selects which patch's footprint this block covers; every thread
// computes the FULL value (both blob contributions) at its pixel, so
// overlapping patches are handled idempotently (both write the same value).
__global__ void RenderNet_stamp_kernel(
    const float* __restrict__ x0, const float* __restrict__ y0,
    const float* __restrict__ x1, const float* __restrict__ y1,
    const int* __restrict__ p_x0, const int* __restrict__ p_y0,
    const int* __restrict__ p_x1, const int* __restrict__ p_y1,
    const int* __restrict__ p_nsteps, const int* __restrict__ p_steep,
    const int* __restrict__ p_imsize, const int* __restrict__ p_lw,
    float* __restrict__ out)
{
    const int lw     = p_lw[0];
    const int center = lw / 2;
    const int pad    = center;
    const int imsize = p_imsize[0];
    const int steep  = p_steep[0];

    // Pixel 0 location: (r,c) = (_y0,_x0) if steep else (_x0,_y0).
    const int r0 = steep ? p_y0[0] : p_x0[0];
    const int c0 = steep ? p_x0[0] : p_y0[0];
    // Pixel 1 location: img[1,0,_x1,_y1] -> row=_x1, col=_y1.
    const int r1 = p_x1[0];
    const int c1 = p_y1[0];

    // v = z * (1/z) in IEEE f32 round-to-nearest, matching jnp exactly
    // (do NOT let --use_fast_math turn this into an approximate rcp).
    const float z0 = __fadd_rn(x0[0], y0[0]);
    const float v0 = __fmul_rn(z0, __fdiv_rn(1.0f, z0));
    const float z1 = __fadd_rn(x1[0], y1[0]);
    const float v1 = __fmul_rn(z1, __fdiv_rn(1.0f, z1));
    const float nf = (float)p_nsteps[0];

    const int per_patch = 3 * lw * lw;   // 3 channels x lw x lw footprint
    const int rc = (blockIdx.x == 0) ? r0 : r1;
    const int cc = (blockIdx.x == 0) ? c0 : c1;

    const size_t plane = (size_t)imsize * (size_t)imsize;

    for (int t = threadIdx.x; t < per_patch; t += blockDim.x) {
        const int ch  = t / (lw * lw);
        const int rem = t % (lw * lw);
        const int ki  = rem / lw;
        const int kj  = rem % lw;

        const int r = rc + ki - pad;
        const int c = cc + kj - pad;
        if (r < 0 || r >= imsize || c < 0 || c >= imsize) continue;

        float total = 0.0f;

        // Contribution from blob0 (scaled by n_steps).
        int di = r - r0 + pad;
        int dj = c - c0 + pad;
        if (di >= 0 && di < lw && dj >= 0 && dj < lw) {
            total = __fmul_rn(nf, __fmul_rn(kernel_val(di, dj, lw, center), v0));
        }
        // Contribution from blob1.
        di = r - r1 + pad;
        dj = c - c1 + pad;
        if (di >= 0 && di < lw && dj >= 0 && dj < lw) {
            total = __fadd_rn(total, __fmul_rn(kernel_val(di, dj, lw, center), v1));
        }

        total = fminf(fmaxf(total, 0.0f), 1.0f);

        out[(size_t)ch * plane + (size_t)r * (size_t)imsize + (size_t)c] = total;
    }
}

extern "C" void kernel_launch(void* const* d_in, const int* in_sizes, int n_in,
                              void* d_out, int out_size)
{
    // Input order (metadata): x0, y0, x1, y1 (f32), _x0, _y0, _x1, _y1,
    // n_steps, steep, imsize, linewidth (i32).
    const float* x0 = (const float*)d_in[0];
    const float* y0 = (const float*)d_in[1];
    const float* x1 = (const float*)d_in[2];
    const float* y1 = (const float*)d_in[3];
    const int* p_x0     = (const int*)d_in[4];
    const int* p_y0     = (const int*)d_in[5];
    const int* p_x1     = (const int*)d_in[6];
    const int* p_y1     = (const int*)d_in[7];
    const int* p_nsteps = (const int*)d_in[8];
    const int* p_steep  = (const int*)d_in[9];
    const int* p_imsize = (const int*)d_in[10];
    const int* p_lw     = (const int*)d_in[11];

    float* out = (float*)d_out;

    // 1) Zero the entire 201 MB output — the HBM-write-bound floor of this
    //    problem. cudaMemsetAsync is graph-capturable.
    cudaMemsetAsync(out, 0, (size_t)out_size * sizeof(float), 0);

    // 2) Stamp the two blobs (tiny: <= 2 x 3*lw*lw pixels). Grid-stride inside
    //    the block covers any linewidth; 1024 threads covers lw<=18 in one pass.
    RenderNet_stamp_kernel<<<2, 1024>>>(x0, y0, x1, y1,
                                        p_x0, p_y0, p_x1, p_y1,
                                        p_nsteps, p_steep, p_imsize, p_lw,
                                        out);
}

// round 6
// speedup vs baseline: 1.0565x; 1.0565x over previous
#include <cuda_runtime.h>
#include <math.h>

// Nested-square smoothing-kernel weight, exactly as Python gen_kernel:
// ring index m = distance to nearest kernel edge; value = (m+1)/(center+1).
__device__ __forceinline__ float kernel_val(int i, int j, int lw, int center) {
    int m = min(min(i, j), min(lw - 1 - i, lw - 1 - j));
    return (float)((1.0 / (double)(center + 1)) * (double)(m + 1));
}

// One block per (row, channel). Zero the whole row with STG.128, then (for the
// <=14 rows that intersect a blob footprint) overwrite the few patch elements.
// The overwriting thread is the same thread that wrote the zeros for that slot,
// so same-thread program order guarantees correctness without any sync.
__global__ void __launch_bounds__(256) RenderNet_fused_kernel(
    const float* __restrict__ x0, const float* __restrict__ y0,
    const float* __restrict__ x1, const float* __restrict__ y1,
    const int* __restrict__ p_x0, const int* __restrict__ p_y0,
    const int* __restrict__ p_x1, const int* __restrict__ p_y1,
    const int* __restrict__ p_nsteps, const int* __restrict__ p_steep,
    const int* __restrict__ p_lw,
    float* __restrict__ out, int imsize)
{
    const int row = blockIdx.x;
    const int ch  = blockIdx.y;
    const int w4  = imsize >> 2;                       // float4 per row
    float4* rowp = reinterpret_cast<float4*>(out)
                 + ((size_t)ch * (size_t)imsize + (size_t)row) * (size_t)w4;

    const float4 z4 = make_float4(0.f, 0.f, 0.f, 0.f);
    const int t = threadIdx.x;

    // Fast path: blast the row with zeros. For imsize=4096, w4=1024 = 4 slots
    // per thread; emit them as 4 independent STG.128 (max store MLP), with a
    // grid-stride fallback for other sizes.
    if (w4 == 1024) {
        rowp[t      ] = z4;
        rowp[t + 256] = z4;
        rowp[t + 512] = z4;
        rowp[t + 768] = z4;
    } else {
        #pragma unroll 4
        for (int s = t; s < w4; s += 256)
            rowp[s] = z4;
    }

    // Row-membership test (tiny scalar loads; L1-hit after first block/SM).
    const int steep = __ldg(p_steep);
    const int lw    = __ldg(p_lw);
    const int pad   = lw >> 1;
    const int r0 = steep ? __ldg(p_y0) : __ldg(p_x0); // img[0,0,r0,c0]
    const int r1 = __ldg(p_x1);                        // img[1,0,_x1,_y1]
    const bool in0 = (unsigned)(row - r0 + pad) < (unsigned)lw;
    const bool in1 = (unsigned)(row - r1 + pad) < (unsigned)lw;
    if (!(in0 || in1)) return;

    // Slow path: this row crosses a blob footprint.
    const int c0 = steep ? __ldg(p_x0) : __ldg(p_y0);
    const int c1 = __ldg(p_y1);

    // v = z * (1/z) in IEEE f32 RN, matching the jnp expression bit-exactly.
    const float za = __fadd_rn(__ldg(x0), __ldg(y0));
    const float v0 = __fmul_rn(za, __fdiv_rn(1.0f, za));
    const float zb = __fadd_rn(__ldg(x1), __ldg(y1));
    const float v1 = __fmul_rn(zb, __fdiv_rn(1.0f, zb));
    const float nf = (float)__ldg(p_nsteps);

    for (int s = t; s < w4; s += 256) {
        const int cbase = s << 2;
        const bool hit0 = in0 && (cbase + 3 >= c0 - pad) && (cbase <= c0 + pad);
        const bool hit1 = in1 && (cbase + 3 >= c1 - pad) && (cbase <= c1 + pad);
        if (!(hit0 || hit1)) continue;

        float4 v = z4;
        float* vp = &v.x;
        #pragma unroll
        for (int e = 0; e < 4; e++) {
            const int c = cbase + e;
            float total = 0.0f;
            int di = row - r0 + pad;
            int dj = c   - c0 + pad;
            if (in0 && (unsigned)dj < (unsigned)lw)
                total = __fmul_rn(nf, __fmul_rn(kernel_val(di, dj, lw, pad), v0));
            di = row - r1 + pad;
            dj = c   - c1 + pad;
            if (in1 && (unsigned)dj < (unsigned)lw)
                total = __fadd_rn(total, __fmul_rn(kernel_val(di, dj, lw, pad), v1));
            vp[e] = fminf(fmaxf(total, 0.0f), 1.0f);
        }
        rowp[s] = v;   // same thread that wrote the zeros for this slot
    }
}

extern "C" void kernel_launch(void* const* d_in, const int* in_sizes, int n_in,
                              void* d_out, int out_size)
{
    // Input order (metadata): x0, y0, x1, y1 (f32), _x0, _y0, _x1, _y1,
    // n_steps, steep, imsize, linewidth (i32).
    const float* x0 = (const float*)d_in[0];
    const float* y0 = (const float*)d_in[1];
    const float* x1 = (const float*)d_in[2];
    const float* y1 = (const float*)d_in[3];
    const int* p_x0     = (const int*)d_in[4];
    const int* p_y0     = (const int*)d_in[5];
    const int* p_x1     = (const int*)d_in[6];
    const int* p_y1     = (const int*)d_in[7];
    const int* p_nsteps = (const int*)d_in[8];
    const int* p_steep  = (const int*)d_in[9];
    const int* p_lw     = (const int*)d_in[11];

    float* out = (float*)d_out;

    // Output is (1, 3, imsize, imsize) f32 -> recover imsize on host.
    const int imsize = (int)(sqrt((double)out_size / 3.0) + 0.5);

    dim3 grid(imsize, 3);
    RenderNet_fused_kernel<<<grid, 256>>>(x0, y0, x1, y1,
                                          p_x0, p_y0, p_x1, p_y1,
                                          p_nsteps, p_steep, p_lw,
                                          out, imsize);
}